// round 1
// baseline (speedup 1.0000x reference)
#include <cuda_runtime.h>
#include <math.h>

#define NG     128
#define NPER   512
#define NNODE  (NG*NPER)      // 65536
#define NEDGE  1048576
#define KTOP   30
#define DNODE  64
#define DEDGE  32
#define D0     96             // DNODE + DEDGE
#define DL     32
#define TOTALF 97             // 32+32+32+1
#define C1N    16
#define C2N    32
#define KW     5
#define PLEN   15             // (30-2)/2+1
#define CONVL  11             // 15-5+1
#define DENSE  352            // 11*32
#define OUTD   128

// ---------------- scratch (no allocation allowed) ----------------
__device__ float g_h96 [NNODE*D0];
__device__ float g_a96 [NNODE*D0];
__device__ float g_hA  [NNODE*DL];
__device__ float g_hB  [NNODE*DL];
__device__ float g_aA  [NNODE*DL];
__device__ float g_aB  [NNODE*DL];
__device__ float g_hcat[NNODE*TOTALF];
__device__ float g_degs[NNODE];
__device__ int   g_topk[NG*KTOP];

__device__ __forceinline__ float* hbuf(int s) { return s == 0 ? g_h96 : (s == 1 ? g_hA : g_hB); }
__device__ __forceinline__ float* abuf(int s) { return s == 0 ? g_a96 : (s == 1 ? g_aA : g_aB); }

// ---------------- init: h96[:, :64]=node_feat, h96[:,64:]=0 ; agg=h ; degs=1 ----------------
__global__ void k_init(const float* __restrict__ nf) {
    int t = blockIdx.x * blockDim.x + threadIdx.x;
    if (t >= NNODE * D0) return;
    int n = t / D0, d = t - n * D0;
    float v = (d < DNODE) ? nf[n * DNODE + d] : 0.f;
    g_h96[t] = v;
    g_a96[t] = v;
    if (d == 0) g_degs[n] = 1.f;
}

// ---------------- e2n scatter: edge_feat -> h96[:,64:96] (and agg), degs += 1 ----------------
__global__ void k_e2n(const float* __restrict__ ef, const int* __restrict__ dst) {
    int t = blockIdx.x * blockDim.x + threadIdx.x;
    if (t >= NEDGE * (DEDGE / 4)) return;
    int e = t >> 3;            // 8 float4 per edge
    int d4 = t & 7;
    int dd = dst[e];
    float4 v = ((const float4*)ef)[e * 8 + d4];
    float* ph = &g_h96[dd * D0 + DNODE + d4 * 4];
    float* pa = &g_a96[dd * D0 + DNODE + d4 * 4];
    atomicAdd(ph + 0, v.x); atomicAdd(ph + 1, v.y); atomicAdd(ph + 2, v.z); atomicAdd(ph + 3, v.w);
    atomicAdd(pa + 0, v.x); atomicAdd(pa + 1, v.y); atomicAdd(pa + 2, v.z); atomicAdd(pa + 3, v.w);
    if (d4 == 0) atomicAdd(&g_degs[dd], 1.f);
}

// ---------------- edge scatter: agg[dst] += h[src] ----------------
template<int DIM>
__global__ void k_scatter(int hsel, int asel,
                          const int* __restrict__ src, const int* __restrict__ dst) {
    const int V = DIM / 4;
    int t = blockIdx.x * blockDim.x + threadIdx.x;
    if (t >= NEDGE * V) return;
    int e = t / V;
    int d4 = t - e * V;
    const float* h = hbuf(hsel);
    float* agg = abuf(asel);
    int s = src[e], d = dst[e];
    float4 v = ((const float4*)h)[s * V + d4];
    float* p = agg + d * DIM + d4 * 4;
    atomicAdd(p + 0, v.x); atomicAdd(p + 1, v.y); atomicAdd(p + 2, v.z); atomicAdd(p + 3, v.w);
}

// ---------------- node update: h' = tanh((agg @ W + b)/deg); writes hout, aggout, hcat slice ----------------
template<int DIN>
__global__ void k_mm(int asel, const float* __restrict__ W, const float* __restrict__ b,
                     int houtsel, int aoutsel, int hcat_off) {
    __shared__ float Ws[DIN * DL];
    __shared__ float bs[DL];
    int tid = threadIdx.x;                  // 256
    for (int i = tid; i < DIN * DL; i += 256) Ws[i] = W[i];
    if (tid < DL) bs[tid] = b[tid];
    __syncthreads();
    const float* agg = abuf(asel);
    float* hout = hbuf(houtsel);
    float* aout = abuf(aoutsel);
    int lane = tid & 31;
    int n = blockIdx.x * 8 + (tid >> 5);
    const float* a = agg + n * DIN;
    float acc = 0.f;
#pragma unroll
    for (int d = 0; d < DIN; d++) acc += a[d] * Ws[d * DL + lane];
    float val = tanhf((acc + bs[lane]) / g_degs[n]);
    hout[n * DL + lane] = val;
    aout[n * DL + lane] = val;
    g_hcat[n * TOTALF + hcat_off + lane] = val;
}

// ---------------- last layer (32 -> 1) ----------------
__global__ void k_mm_last(int asel, const float* __restrict__ W, const float* __restrict__ b) {
    int n = blockIdx.x * blockDim.x + threadIdx.x;
    if (n >= NNODE) return;
    const float* a = abuf(asel) + n * DL;
    float acc = 0.f;
#pragma unroll
    for (int d = 0; d < DL; d++) acc += a[d] * W[d];
    g_hcat[n * TOTALF + 96] = tanhf((acc + b[0]) / g_degs[n]);
}

// ---------------- per-group top-K on channel 96 (value desc, index asc ties) ----------------
__global__ void k_topk() {
    __shared__ float v[NPER];
    __shared__ int   ix[NPER];
    int g = blockIdx.x, tid = threadIdx.x;      // 256 threads
    for (int i = tid; i < NPER; i += 256) {
        v[i] = g_hcat[(g * NPER + i) * TOTALF + 96];
        ix[i] = i;
    }
    __syncthreads();
    for (int k = 2; k <= NPER; k <<= 1) {
        for (int j = k >> 1; j > 0; j >>= 1) {
            for (int i = tid; i < NPER; i += 256) {
                int p = i ^ j;
                if (p > i) {
                    float va = v[i], vb = v[p];
                    int ia = ix[i], ib = ix[p];
                    bool a_first = (va > vb) || (va == vb && ia < ib);
                    bool up = ((i & k) == 0);
                    if (up ? !a_first : a_first) {
                        v[i] = vb; v[p] = va;
                        ix[i] = ib; ix[p] = ia;
                    }
                }
            }
            __syncthreads();
        }
    }
    if (tid < KTOP) g_topk[g * KTOP + tid] = ix[tid];
}

// ---------------- head: gather pooled, 1x1 conv, maxpool, conv5, dense ----------------
__global__ void k_head(const float* __restrict__ cw1, const float* __restrict__ cb1,
                       const float* __restrict__ cw2, const float* __restrict__ cb2,
                       const float* __restrict__ ow,  const float* __restrict__ ob,
                       float* __restrict__ out) {
    __shared__ float pooled[KTOP][TOTALF];
    __shared__ float c1s[C1N][KTOP];
    __shared__ float c1p[C1N][PLEN];
    __shared__ float c2s[DENSE];
    int g = blockIdx.x, tid = threadIdx.x;       // 128 threads

    for (int t = tid; t < KTOP * TOTALF; t += 128) {
        int kk = t / TOTALF, d = t - kk * TOTALF;
        int node = g * NPER + g_topk[g * KTOP + kk];
        pooled[kk][d] = g_hcat[node * TOTALF + d];
    }
    __syncthreads();

    for (int t = tid; t < C1N * KTOP; t += 128) {
        int o = t / KTOP, kk = t - o * KTOP;
        float s = cb1[o];
#pragma unroll 8
        for (int d = 0; d < TOTALF; d++) s += pooled[kk][d] * cw1[o * TOTALF + d];
        c1s[o][kk] = fmaxf(s, 0.f);
    }
    __syncthreads();

    for (int t = tid; t < C1N * PLEN; t += 128) {
        int o = t / PLEN, j = t - o * PLEN;
        c1p[o][j] = fmaxf(c1s[o][2 * j], c1s[o][2 * j + 1]);
    }
    __syncthreads();

    for (int t = tid; t < C2N * CONVL; t += 128) {
        int o = t / CONVL, j = t - o * CONVL;
        float s = cb2[o];
#pragma unroll
        for (int i = 0; i < C1N; i++)
#pragma unroll
            for (int u = 0; u < KW; u++)
                s += c1p[i][j + u] * cw2[(o * C1N + i) * KW + u];
        c2s[o * CONVL + j] = fmaxf(s, 0.f);
    }
    __syncthreads();

    {
        int u = tid;
        float s = ob[u];
#pragma unroll 8
        for (int f = 0; f < DENSE; f++) s += c2s[f] * ow[f * OUTD + u];
        out[g * OUTD + u] = fmaxf(s, 0.f);     // relu(relu(x)) == relu(x)
    }
}

// ---------------- launch ----------------
extern "C" void kernel_launch(void* const* d_in, const int* in_sizes, int n_in,
                              void* d_out, int out_size) {
    const float* node_feat = (const float*)d_in[0];
    const float* edge_feat = (const float*)d_in[1];
    const int*   edge_src  = (const int*)  d_in[2];
    const int*   edge_dst  = (const int*)  d_in[3];
    const float* W0 = (const float*)d_in[4];
    const float* b0 = (const float*)d_in[5];
    const float* W1 = (const float*)d_in[6];
    const float* b1 = (const float*)d_in[7];
    const float* W2 = (const float*)d_in[8];
    const float* b2 = (const float*)d_in[9];
    const float* W3 = (const float*)d_in[10];
    const float* b3 = (const float*)d_in[11];
    const float* cw1 = (const float*)d_in[12];
    const float* cb1 = (const float*)d_in[13];
    const float* cw2 = (const float*)d_in[14];
    const float* cb2 = (const float*)d_in[15];
    const float* ow  = (const float*)d_in[16];
    const float* ob  = (const float*)d_in[17];
    float* out = (float*)d_out;

    k_init<<<(NNODE * D0 + 255) / 256, 256>>>(node_feat);
    k_e2n<<<(NEDGE * 8 + 255) / 256, 256>>>(edge_feat, edge_dst);

    // layer 0: h96 -> hA (hcat[0:32))
    k_scatter<D0><<<(NEDGE * 24 + 255) / 256, 256>>>(0, 0, edge_src, edge_dst);
    k_mm<D0><<<NNODE / 8, 256>>>(0, W0, b0, 1, 1, 0);

    // layer 1: hA -> hB (hcat[32:64))
    k_scatter<DL><<<(NEDGE * 8 + 255) / 256, 256>>>(1, 1, edge_src, edge_dst);
    k_mm<DL><<<NNODE / 8, 256>>>(1, W1, b1, 2, 2, 32);

    // layer 2: hB -> hA (hcat[64:96))
    k_scatter<DL><<<(NEDGE * 8 + 255) / 256, 256>>>(2, 2, edge_src, edge_dst);
    k_mm<DL><<<NNODE / 8, 256>>>(2, W2, b2, 1, 1, 64);

    // layer 3: hA -> hcat[96]
    k_scatter<DL><<<(NEDGE * 8 + 255) / 256, 256>>>(1, 1, edge_src, edge_dst);
    k_mm_last<<<NNODE / 256, 256>>>(1, W3, b3);

    k_topk<<<NG, 256>>>();
    k_head<<<NG, 128>>>(cw1, cb1, cw2, cb2, ow, ob, out);
}

// round 2
// speedup vs baseline: 2.5458x; 2.5458x over previous
#include <cuda_runtime.h>
#include <math.h>

#define NG     128
#define NPER   512
#define NNODE  (NG*NPER)      // 65536
#define NEDGE  1048576
#define KTOP   30
#define DNODE  64
#define DEDGE  32
#define D0     96
#define DL     32
#define TOTALF 97
#define C1N    16
#define C2N    32
#define KW     5
#define PLEN   15
#define CONVL  11
#define DENSE  352
#define OUTD   128

// ---------------- scratch ----------------
__device__ float g_h96 [NNODE*D0];
__device__ float g_hA  [NNODE*DL];
__device__ float g_hB  [NNODE*DL];
__device__ float g_hcat[NNODE*TOTALF];
__device__ float g_degs[NNODE];
__device__ int   g_cnt [NNODE];
__device__ int   g_row [NNODE];     // exclusive row start
__device__ int   g_cur [NNODE];
__device__ int   g_bsum[64];
__device__ int   g_boff[64];
__device__ int   g_csrc[NEDGE];     // src id in dst-sorted order
__device__ int   g_ceid[NEDGE];     // edge id in dst-sorted order
__device__ int   g_topk[NG*KTOP];

__device__ __forceinline__ float* hsel(int s) { return s == 0 ? g_hA : g_hB; }

// ---------------- CSR build ----------------
__global__ void k_zero() { g_cnt[blockIdx.x * 1024 + threadIdx.x] = 0; }

__global__ void k_hist(const int* __restrict__ dst) {
    int e = blockIdx.x * 1024 + threadIdx.x;
    atomicAdd(&g_cnt[dst[e]], 1);
}

__global__ void k_scanA() {
    __shared__ int s[1024];
    int i = blockIdx.x * 1024 + threadIdx.x;
    int v = g_cnt[i];
    s[threadIdx.x] = v; __syncthreads();
    for (int off = 1; off < 1024; off <<= 1) {
        int t = (threadIdx.x >= off) ? s[threadIdx.x - off] : 0;
        __syncthreads();
        s[threadIdx.x] += t;
        __syncthreads();
    }
    g_row[i] = s[threadIdx.x] - v;                 // exclusive within block
    if (threadIdx.x == 1023) g_bsum[blockIdx.x] = s[1023];
}

__global__ void k_scanB() {
    if (threadIdx.x == 0) {
        int acc = 0;
        for (int i = 0; i < 64; i++) { g_boff[i] = acc; acc += g_bsum[i]; }
    }
}

__global__ void k_scanC() {
    int i = blockIdx.x * 1024 + threadIdx.x;
    int rs = g_row[i] + g_boff[i >> 10];
    g_row[i] = rs;
    g_cur[i] = rs;
    g_degs[i] = (float)g_cnt[i] + 1.f;
}

__global__ void k_fill(const int* __restrict__ src, const int* __restrict__ dst) {
    int e = blockIdx.x * 1024 + threadIdx.x;
    int d = dst[e];
    int p = atomicAdd(&g_cur[d], 1);
    g_csrc[p] = src[e];
    g_ceid[p] = e;
}

// ---------------- build h96: [node_feat | e2n gather] ----------------
__global__ void k_build_h96(const float* __restrict__ nf, const float* __restrict__ ef) {
    int w = threadIdx.x >> 5, lane = threadIdx.x & 31;
    int n = blockIdx.x * 8 + w;
    float f0 = nf[n * DNODE + lane];
    float f1 = nf[n * DNODE + 32 + lane];
    int beg = g_row[n], end = beg + g_cnt[n];
    float acc = 0.f;
    int j = beg;
    for (; j + 3 < end; j += 4) {
        int e0 = g_ceid[j], e1 = g_ceid[j+1], e2 = g_ceid[j+2], e3 = g_ceid[j+3];
        float v0 = ef[e0 * DEDGE + lane];
        float v1 = ef[e1 * DEDGE + lane];
        float v2 = ef[e2 * DEDGE + lane];
        float v3 = ef[e3 * DEDGE + lane];
        acc += v0 + v1 + v2 + v3;
    }
    for (; j < end; j++) acc += ef[g_ceid[j] * DEDGE + lane];
    float* hp = &g_h96[n * D0];
    hp[lane] = f0; hp[32 + lane] = f1; hp[64 + lane] = acc;
}

// ---------------- layer 0: gather(h96) + matvec 96->32 + tanh ----------------
__global__ void k_layer0(const float* __restrict__ W, const float* __restrict__ b) {
    __shared__ float Ws[D0 * DL];
    __shared__ float bs[DL];
    __shared__ float agg[8][D0];
    int tid = threadIdx.x;
    for (int i = tid; i < D0 * DL; i += 256) Ws[i] = W[i];
    if (tid < DL) bs[tid] = b[tid];
    __syncthreads();
    int w = tid >> 5, lane = tid & 31;
    int n = blockIdx.x * 8 + w;
    const float* hp = &g_h96[n * D0];
    float a0 = hp[lane], a1 = hp[32 + lane], a2 = hp[64 + lane];
    int beg = g_row[n], end = beg + g_cnt[n];
    int j = beg;
    for (; j + 1 < end; j += 2) {
        int s0 = g_csrc[j], s1 = g_csrc[j + 1];
        const float* p0 = &g_h96[s0 * D0];
        const float* p1 = &g_h96[s1 * D0];
        float x0 = p0[lane], x1 = p0[32 + lane], x2 = p0[64 + lane];
        float y0 = p1[lane], y1 = p1[32 + lane], y2 = p1[64 + lane];
        a0 += x0 + y0; a1 += x1 + y1; a2 += x2 + y2;
    }
    for (; j < end; j++) {
        const float* p0 = &g_h96[g_csrc[j] * D0];
        a0 += p0[lane]; a1 += p0[32 + lane]; a2 += p0[64 + lane];
    }
    agg[w][lane] = a0; agg[w][32 + lane] = a1; agg[w][64 + lane] = a2;
    __syncwarp();
    float acc = bs[lane];
#pragma unroll
    for (int d = 0; d < D0; d++) acc += agg[w][d] * Ws[d * DL + lane];
    float val = tanhf(acc / g_degs[n]);
    g_hA[n * DL + lane] = val;
    g_hcat[n * TOTALF + lane] = val;
}

// ---------------- layers 1-2: gather(32) + matvec 32->32 + tanh ----------------
__global__ void k_layerL(int insel, int outsel, int hcat_off,
                         const float* __restrict__ W, const float* __restrict__ b) {
    __shared__ float Ws[DL * DL];
    __shared__ float bs[DL];
    __shared__ float agg[8][DL];
    int tid = threadIdx.x;
    for (int i = tid; i < DL * DL; i += 256) Ws[i] = W[i];
    if (tid < DL) bs[tid] = b[tid];
    __syncthreads();
    int w = tid >> 5, lane = tid & 31;
    int n = blockIdx.x * 8 + w;
    const float* h = hsel(insel);
    float* hout = hsel(outsel);
    float a = h[n * DL + lane];
    int beg = g_row[n], end = beg + g_cnt[n];
    int j = beg;
    for (; j + 3 < end; j += 4) {
        int s0 = g_csrc[j], s1 = g_csrc[j+1], s2 = g_csrc[j+2], s3 = g_csrc[j+3];
        float x0 = h[s0 * DL + lane];
        float x1 = h[s1 * DL + lane];
        float x2 = h[s2 * DL + lane];
        float x3 = h[s3 * DL + lane];
        a += x0 + x1 + x2 + x3;
    }
    for (; j < end; j++) a += h[g_csrc[j] * DL + lane];
    agg[w][lane] = a;
    __syncwarp();
    float acc = bs[lane];
#pragma unroll
    for (int d = 0; d < DL; d++) acc += agg[w][d] * Ws[d * DL + lane];
    float val = tanhf(acc / g_degs[n]);
    hout[n * DL + lane] = val;
    g_hcat[n * TOTALF + hcat_off + lane] = val;
}

// ---------------- layer 3: gather(32) + dot 32->1 + tanh ----------------
__global__ void k_layer_last(const float* __restrict__ W, const float* __restrict__ b) {
    int tid = threadIdx.x;
    int w = tid >> 5, lane = tid & 31;
    int n = blockIdx.x * 8 + w;
    const float* h = g_hA;
    float a = h[n * DL + lane];
    int beg = g_row[n], end = beg + g_cnt[n];
    int j = beg;
    for (; j + 3 < end; j += 4) {
        int s0 = g_csrc[j], s1 = g_csrc[j+1], s2 = g_csrc[j+2], s3 = g_csrc[j+3];
        float x0 = h[s0 * DL + lane];
        float x1 = h[s1 * DL + lane];
        float x2 = h[s2 * DL + lane];
        float x3 = h[s3 * DL + lane];
        a += x0 + x1 + x2 + x3;
    }
    for (; j < end; j++) a += h[g_csrc[j] * DL + lane];
    float v = a * W[lane];
#pragma unroll
    for (int off = 16; off > 0; off >>= 1) v += __shfl_xor_sync(0xffffffffu, v, off);
    if (lane == 0)
        g_hcat[n * TOTALF + 96] = tanhf((v + b[0]) / g_degs[n]);
}

// ---------------- per-group top-K (value desc, index asc ties) ----------------
__global__ void k_topk() {
    __shared__ float v[NPER];
    __shared__ int   ix[NPER];
    int g = blockIdx.x, tid = threadIdx.x;      // 256 threads
    for (int i = tid; i < NPER; i += 256) {
        v[i] = g_hcat[(g * NPER + i) * TOTALF + 96];
        ix[i] = i;
    }
    __syncthreads();
    for (int k = 2; k <= NPER; k <<= 1) {
        for (int j = k >> 1; j > 0; j >>= 1) {
            for (int i = tid; i < NPER; i += 256) {
                int p = i ^ j;
                if (p > i) {
                    float va = v[i], vb = v[p];
                    int ia = ix[i], ib = ix[p];
                    bool a_first = (va > vb) || (va == vb && ia < ib);
                    bool up = ((i & k) == 0);
                    if (up ? !a_first : a_first) {
                        v[i] = vb; v[p] = va;
                        ix[i] = ib; ix[p] = ia;
                    }
                }
            }
            __syncthreads();
        }
    }
    if (tid < KTOP) g_topk[g * KTOP + tid] = ix[tid];
}

// ---------------- head ----------------
__global__ void k_head(const float* __restrict__ cw1, const float* __restrict__ cb1,
                       const float* __restrict__ cw2, const float* __restrict__ cb2,
                       const float* __restrict__ ow,  const float* __restrict__ ob,
                       float* __restrict__ out) {
    __shared__ float pooled[KTOP][TOTALF];
    __shared__ float c1s[C1N][KTOP];
    __shared__ float c1p[C1N][PLEN];
    __shared__ float c2s[DENSE];
    int g = blockIdx.x, tid = threadIdx.x;       // 128 threads

    for (int t = tid; t < KTOP * TOTALF; t += 128) {
        int kk = t / TOTALF, d = t - kk * TOTALF;
        int node = g * NPER + g_topk[g * KTOP + kk];
        pooled[kk][d] = g_hcat[node * TOTALF + d];
    }
    __syncthreads();

    for (int t = tid; t < C1N * KTOP; t += 128) {
        int o = t / KTOP, kk = t - o * KTOP;
        float s = cb1[o];
#pragma unroll 8
        for (int d = 0; d < TOTALF; d++) s += pooled[kk][d] * cw1[o * TOTALF + d];
        c1s[o][kk] = fmaxf(s, 0.f);
    }
    __syncthreads();

    for (int t = tid; t < C1N * PLEN; t += 128) {
        int o = t / PLEN, j = t - o * PLEN;
        c1p[o][j] = fmaxf(c1s[o][2 * j], c1s[o][2 * j + 1]);
    }
    __syncthreads();

    for (int t = tid; t < C2N * CONVL; t += 128) {
        int o = t / CONVL, j = t - o * CONVL;
        float s = cb2[o];
#pragma unroll
        for (int i = 0; i < C1N; i++)
#pragma unroll
            for (int u = 0; u < KW; u++)
                s += c1p[i][j + u] * cw2[(o * C1N + i) * KW + u];
        c2s[o * CONVL + j] = fmaxf(s, 0.f);
    }
    __syncthreads();

    {
        int u = tid;
        float s = ob[u];
#pragma unroll 8
        for (int f = 0; f < DENSE; f++) s += c2s[f] * ow[f * OUTD + u];
        out[g * OUTD + u] = fmaxf(s, 0.f);
    }
}

// ---------------- launch ----------------
extern "C" void kernel_launch(void* const* d_in, const int* in_sizes, int n_in,
                              void* d_out, int out_size) {
    const float* node_feat = (const float*)d_in[0];
    const float* edge_feat = (const float*)d_in[1];
    const int*   edge_src  = (const int*)  d_in[2];
    const int*   edge_dst  = (const int*)  d_in[3];
    const float* W0 = (const float*)d_in[4];
    const float* b0 = (const float*)d_in[5];
    const float* W1 = (const float*)d_in[6];
    const float* b1 = (const float*)d_in[7];
    const float* W2 = (const float*)d_in[8];
    const float* b2 = (const float*)d_in[9];
    const float* W3 = (const float*)d_in[10];
    const float* b3 = (const float*)d_in[11];
    const float* cw1 = (const float*)d_in[12];
    const float* cb1 = (const float*)d_in[13];
    const float* cw2 = (const float*)d_in[14];
    const float* cb2 = (const float*)d_in[15];
    const float* ow  = (const float*)d_in[16];
    const float* ob  = (const float*)d_in[17];
    float* out = (float*)d_out;

    // CSR build (dst-sorted)
    k_zero <<<64, 1024>>>();
    k_hist <<<1024, 1024>>>(edge_dst);
    k_scanA<<<64, 1024>>>();
    k_scanB<<<1, 64>>>();
    k_scanC<<<64, 1024>>>();
    k_fill <<<1024, 1024>>>(edge_src, edge_dst);

    // GNN layers (gather-based, fused agg+matvec)
    k_build_h96<<<NNODE / 8, 256>>>(node_feat, edge_feat);
    k_layer0   <<<NNODE / 8, 256>>>(W0, b0);
    k_layerL   <<<NNODE / 8, 256>>>(0, 1, 32, W1, b1);   // hA -> hB
    k_layerL   <<<NNODE / 8, 256>>>(1, 0, 64, W2, b2);   // hB -> hA
    k_layer_last<<<NNODE / 8, 256>>>(W3, b3);            // hA -> hcat[96]

    k_topk<<<NG, 256>>>();
    k_head<<<NG, 128>>>(cw1, cb1, cw2, cb2, ow, ob, out);
}

// round 3
// speedup vs baseline: 2.6891x; 1.0563x over previous
#include <cuda_runtime.h>
#include <math.h>

#define NG     128
#define NPER   512
#define NNODE  (NG*NPER)      // 65536
#define NEDGE  1048576
#define KTOP   30
#define DNODE  64
#define DEDGE  32
#define D0     96
#define DL     32
#define TOTALF 97
#define C1N    16
#define C2N    32
#define KW     5
#define PLEN   15
#define CONVL  11
#define DENSE  352
#define OUTD   128

// ---------------- scratch ----------------
__device__ float g_h96 [NNODE*D0];
__device__ float g_hA  [NNODE*DL];
__device__ float g_hB  [NNODE*DL];
__device__ float g_hcat[NNODE*TOTALF];
__device__ float g_degs[NNODE];
__device__ int   g_cnt [NNODE];
__device__ int   g_row [NNODE];
__device__ int   g_cur [NNODE];
__device__ int   g_bsum[64];
__device__ int   g_csrc[NEDGE];
__device__ int   g_ceid[NEDGE];

__device__ __forceinline__ float* hsel(int s) { return s == 0 ? g_hA : g_hB; }

// ---------------- CSR build ----------------
__global__ void k_hist(const int* __restrict__ dst) {
    int e = blockIdx.x * 1024 + threadIdx.x;
    atomicAdd(&g_cnt[dst[e]], 1);
}

__global__ void k_scanA() {
    __shared__ int s[1024];
    int i = blockIdx.x * 1024 + threadIdx.x;
    int v = g_cnt[i];
    s[threadIdx.x] = v; __syncthreads();
    for (int off = 1; off < 1024; off <<= 1) {
        int t = (threadIdx.x >= off) ? s[threadIdx.x - off] : 0;
        __syncthreads();
        s[threadIdx.x] += t;
        __syncthreads();
    }
    g_row[i] = s[threadIdx.x] - v;                 // exclusive within block
    if (threadIdx.x == 1023) g_bsum[blockIdx.x] = s[1023];
}

// per-block parallel offset reduction (no serial single-thread kernel)
__global__ void k_scanC() {
    __shared__ int sb[64];
    __shared__ int off;
    if (threadIdx.x < 64)
        sb[threadIdx.x] = (threadIdx.x < blockIdx.x) ? g_bsum[threadIdx.x] : 0;
    __syncthreads();
    if (threadIdx.x < 32) {
        int v = sb[threadIdx.x] + sb[threadIdx.x + 32];
#pragma unroll
        for (int o = 16; o > 0; o >>= 1) v += __shfl_down_sync(0xffffffffu, v, o);
        if (threadIdx.x == 0) off = v;
    }
    __syncthreads();
    int i = blockIdx.x * 1024 + threadIdx.x;
    int rs = g_row[i] + off;
    g_row[i] = rs;
    g_cur[i] = rs;
    g_degs[i] = (float)g_cnt[i] + 1.f;
}

__global__ void k_fill(const int* __restrict__ src, const int* __restrict__ dst) {
    int e = blockIdx.x * 1024 + threadIdx.x;
    int d = dst[e];
    int p = atomicAdd(&g_cur[d], 1);
    g_csrc[p] = src[e];
    g_ceid[p] = e;
}

// ---------------- build h96: [node_feat | e2n gather] ----------------
__global__ void k_build_h96(const float* __restrict__ nf, const float* __restrict__ ef) {
    int w = threadIdx.x >> 5, lane = threadIdx.x & 31;
    int n = blockIdx.x * 8 + w;
    float f0 = nf[n * DNODE + lane];
    float f1 = nf[n * DNODE + 32 + lane];
    int beg = g_row[n], end = beg + g_cnt[n];
    float acc = 0.f;
    int j = beg;
    for (; j + 7 < end; j += 8) {
        int e0 = g_ceid[j],   e1 = g_ceid[j+1], e2 = g_ceid[j+2], e3 = g_ceid[j+3];
        int e4 = g_ceid[j+4], e5 = g_ceid[j+5], e6 = g_ceid[j+6], e7 = g_ceid[j+7];
        float v0 = ef[e0 * DEDGE + lane];
        float v1 = ef[e1 * DEDGE + lane];
        float v2 = ef[e2 * DEDGE + lane];
        float v3 = ef[e3 * DEDGE + lane];
        float v4 = ef[e4 * DEDGE + lane];
        float v5 = ef[e5 * DEDGE + lane];
        float v6 = ef[e6 * DEDGE + lane];
        float v7 = ef[e7 * DEDGE + lane];
        acc += ((v0 + v1) + (v2 + v3)) + ((v4 + v5) + (v6 + v7));
    }
    for (; j < end; j++) acc += ef[g_ceid[j] * DEDGE + lane];
    float* hp = &g_h96[n * D0];
    hp[lane] = f0; hp[32 + lane] = f1; hp[64 + lane] = acc;
}

// ---------------- layer 0: gather(h96) + matvec 96->32 + tanh ----------------
__global__ void k_layer0(const float* __restrict__ W, const float* __restrict__ b) {
    __shared__ float Ws[D0 * DL];
    __shared__ float bs[DL];
    __shared__ float agg[8][D0];
    int tid = threadIdx.x;
    for (int i = tid; i < D0 * DL; i += 256) Ws[i] = W[i];
    if (tid < DL) bs[tid] = b[tid];
    __syncthreads();
    int w = tid >> 5, lane = tid & 31;
    int n = blockIdx.x * 8 + w;
    const float* hp = &g_h96[n * D0];
    float a0 = hp[lane], a1 = hp[32 + lane], a2 = hp[64 + lane];
    int beg = g_row[n], end = beg + g_cnt[n];
    int j = beg;
    for (; j + 3 < end; j += 4) {
        int s0 = g_csrc[j], s1 = g_csrc[j+1], s2 = g_csrc[j+2], s3 = g_csrc[j+3];
        const float* p0 = &g_h96[s0 * D0];
        const float* p1 = &g_h96[s1 * D0];
        const float* p2 = &g_h96[s2 * D0];
        const float* p3 = &g_h96[s3 * D0];
        float x00 = p0[lane], x01 = p0[32+lane], x02 = p0[64+lane];
        float x10 = p1[lane], x11 = p1[32+lane], x12 = p1[64+lane];
        float x20 = p2[lane], x21 = p2[32+lane], x22 = p2[64+lane];
        float x30 = p3[lane], x31 = p3[32+lane], x32 = p3[64+lane];
        a0 += (x00 + x10) + (x20 + x30);
        a1 += (x01 + x11) + (x21 + x31);
        a2 += (x02 + x12) + (x22 + x32);
    }
    for (; j < end; j++) {
        const float* p0 = &g_h96[g_csrc[j] * D0];
        a0 += p0[lane]; a1 += p0[32 + lane]; a2 += p0[64 + lane];
    }
    agg[w][lane] = a0; agg[w][32 + lane] = a1; agg[w][64 + lane] = a2;
    __syncwarp();
    float acc = bs[lane];
#pragma unroll
    for (int d = 0; d < D0; d++) acc += agg[w][d] * Ws[d * DL + lane];
    float val = tanhf(acc / g_degs[n]);
    g_hA[n * DL + lane] = val;
    g_hcat[n * TOTALF + lane] = val;
}

// ---------------- layers 1-2: gather(32) + matvec 32->32 + tanh ----------------
__global__ void k_layerL(int insel, int outsel, int hcat_off,
                         const float* __restrict__ W, const float* __restrict__ b) {
    __shared__ float Ws[DL * DL];
    __shared__ float bs[DL];
    __shared__ float agg[8][DL];
    int tid = threadIdx.x;
    for (int i = tid; i < DL * DL; i += 256) Ws[i] = W[i];
    if (tid < DL) bs[tid] = b[tid];
    __syncthreads();
    int w = tid >> 5, lane = tid & 31;
    int n = blockIdx.x * 8 + w;
    const float* h = hsel(insel);
    float* hout = hsel(outsel);
    float a = h[n * DL + lane];
    int beg = g_row[n], end = beg + g_cnt[n];
    int j = beg;
    for (; j + 7 < end; j += 8) {
        int s0 = g_csrc[j],   s1 = g_csrc[j+1], s2 = g_csrc[j+2], s3 = g_csrc[j+3];
        int s4 = g_csrc[j+4], s5 = g_csrc[j+5], s6 = g_csrc[j+6], s7 = g_csrc[j+7];
        float x0 = h[s0 * DL + lane];
        float x1 = h[s1 * DL + lane];
        float x2 = h[s2 * DL + lane];
        float x3 = h[s3 * DL + lane];
        float x4 = h[s4 * DL + lane];
        float x5 = h[s5 * DL + lane];
        float x6 = h[s6 * DL + lane];
        float x7 = h[s7 * DL + lane];
        a += ((x0 + x1) + (x2 + x3)) + ((x4 + x5) + (x6 + x7));
    }
    for (; j < end; j++) a += h[g_csrc[j] * DL + lane];
    agg[w][lane] = a;
    __syncwarp();
    float acc = bs[lane];
#pragma unroll
    for (int d = 0; d < DL; d++) acc += agg[w][d] * Ws[d * DL + lane];
    float val = tanhf(acc / g_degs[n]);
    hout[n * DL + lane] = val;
    g_hcat[n * TOTALF + hcat_off + lane] = val;
}

// ---------------- layer 3: gather(32) + dot 32->1 + tanh ----------------
__global__ void k_layer_last(const float* __restrict__ W, const float* __restrict__ b) {
    int tid = threadIdx.x;
    int w = tid >> 5, lane = tid & 31;
    int n = blockIdx.x * 8 + w;
    const float* h = g_hA;
    float a = h[n * DL + lane];
    int beg = g_row[n], end = beg + g_cnt[n];
    int j = beg;
    for (; j + 7 < end; j += 8) {
        int s0 = g_csrc[j],   s1 = g_csrc[j+1], s2 = g_csrc[j+2], s3 = g_csrc[j+3];
        int s4 = g_csrc[j+4], s5 = g_csrc[j+5], s6 = g_csrc[j+6], s7 = g_csrc[j+7];
        float x0 = h[s0 * DL + lane];
        float x1 = h[s1 * DL + lane];
        float x2 = h[s2 * DL + lane];
        float x3 = h[s3 * DL + lane];
        float x4 = h[s4 * DL + lane];
        float x5 = h[s5 * DL + lane];
        float x6 = h[s6 * DL + lane];
        float x7 = h[s7 * DL + lane];
        a += ((x0 + x1) + (x2 + x3)) + ((x4 + x5) + (x6 + x7));
    }
    for (; j < end; j++) a += h[g_csrc[j] * DL + lane];
    float v = a * W[lane];
#pragma unroll
    for (int off = 16; off > 0; off >>= 1) v += __shfl_xor_sync(0xffffffffu, v, off);
    if (lane == 0)
        g_hcat[n * TOTALF + 96] = tanhf((v + b[0]) / g_degs[n]);
}

// ---------------- fused per-group topk + head (one block per group, 256 thr) ----------------
__global__ void k_tail(const float* __restrict__ cw1, const float* __restrict__ cb1,
                       const float* __restrict__ cw2, const float* __restrict__ cb2,
                       const float* __restrict__ ow,  const float* __restrict__ ob,
                       float* __restrict__ out) {
    __shared__ float v[NPER];
    __shared__ int   ix[NPER];
    __shared__ float pooled[KTOP][TOTALF];
    __shared__ float c1s[C1N][KTOP];
    __shared__ float c1p[C1N][PLEN];
    __shared__ float c2s[DENSE];
    int g = blockIdx.x, tid = threadIdx.x;      // 256 threads

    // ---- top-K on channel 96 (value desc, index asc ties) ----
    for (int i = tid; i < NPER; i += 256) {
        v[i] = g_hcat[(g * NPER + i) * TOTALF + 96];
        ix[i] = i;
    }
    __syncthreads();
    for (int k = 2; k <= NPER; k <<= 1) {
        for (int j = k >> 1; j > 0; j >>= 1) {
            for (int i = tid; i < NPER; i += 256) {
                int p = i ^ j;
                if (p > i) {
                    float va = v[i], vb = v[p];
                    int ia = ix[i], ib = ix[p];
                    bool a_first = (va > vb) || (va == vb && ia < ib);
                    bool up = ((i & k) == 0);
                    if (up ? !a_first : a_first) {
                        v[i] = vb; v[p] = va;
                        ix[i] = ib; ix[p] = ia;
                    }
                }
            }
            __syncthreads();
        }
    }

    // ---- gather pooled ----
    for (int t = tid; t < KTOP * TOTALF; t += 256) {
        int kk = t / TOTALF, d = t - kk * TOTALF;
        int node = g * NPER + ix[kk];
        pooled[kk][d] = g_hcat[node * TOTALF + d];
    }
    __syncthreads();

    // ---- 1x1 conv (16 ch over 97 feats) + relu ----
    for (int t = tid; t < C1N * KTOP; t += 256) {
        int o = t / KTOP, kk = t - o * KTOP;
        float s = cb1[o];
#pragma unroll 8
        for (int d = 0; d < TOTALF; d++) s += pooled[kk][d] * cw1[o * TOTALF + d];
        c1s[o][kk] = fmaxf(s, 0.f);
    }
    __syncthreads();

    // ---- maxpool /2 ----
    for (int t = tid; t < C1N * PLEN; t += 256) {
        int o = t / PLEN, j = t - o * PLEN;
        c1p[o][j] = fmaxf(c1s[o][2 * j], c1s[o][2 * j + 1]);
    }
    __syncthreads();

    // ---- conv k=5 + relu ----
    for (int t = tid; t < C2N * CONVL; t += 256) {
        int o = t / CONVL, j = t - o * CONVL;
        float s = cb2[o];
#pragma unroll
        for (int i = 0; i < C1N; i++)
#pragma unroll
            for (int u = 0; u < KW; u++)
                s += c1p[i][j + u] * cw2[(o * C1N + i) * KW + u];
        c2s[o * CONVL + j] = fmaxf(s, 0.f);
    }
    __syncthreads();

    // ---- dense 352->128 + relu ----
    if (tid < OUTD) {
        int u = tid;
        float s = ob[u];
#pragma unroll 8
        for (int f = 0; f < DENSE; f++) s += c2s[f] * ow[f * OUTD + u];
        out[g * OUTD + u] = fmaxf(s, 0.f);
    }
}

// ---------------- launch ----------------
extern "C" void kernel_launch(void* const* d_in, const int* in_sizes, int n_in,
                              void* d_out, int out_size) {
    const float* node_feat = (const float*)d_in[0];
    const float* edge_feat = (const float*)d_in[1];
    const int*   edge_src  = (const int*)  d_in[2];
    const int*   edge_dst  = (const int*)  d_in[3];
    const float* W0 = (const float*)d_in[4];
    const float* b0 = (const float*)d_in[5];
    const float* W1 = (const float*)d_in[6];
    const float* b1 = (const float*)d_in[7];
    const float* W2 = (const float*)d_in[8];
    const float* b2 = (const float*)d_in[9];
    const float* W3 = (const float*)d_in[10];
    const float* b3 = (const float*)d_in[11];
    const float* cw1 = (const float*)d_in[12];
    const float* cb1 = (const float*)d_in[13];
    const float* cw2 = (const float*)d_in[14];
    const float* cb2 = (const float*)d_in[15];
    const float* ow  = (const float*)d_in[16];
    const float* ob  = (const float*)d_in[17];
    float* out = (float*)d_out;

    void* cnt_ptr = nullptr;
    cudaGetSymbolAddress(&cnt_ptr, g_cnt);
    cudaMemsetAsync(cnt_ptr, 0, NNODE * sizeof(int), 0);

    k_hist <<<1024, 1024>>>(edge_dst);
    k_scanA<<<64, 1024>>>();
    k_scanC<<<64, 1024>>>();
    k_fill <<<1024, 1024>>>(edge_src, edge_dst);

    k_build_h96<<<NNODE / 8, 256>>>(node_feat, edge_feat);
    k_layer0   <<<NNODE / 8, 256>>>(W0, b0);
    k_layerL   <<<NNODE / 8, 256>>>(0, 1, 32, W1, b1);   // hA -> hB
    k_layerL   <<<NNODE / 8, 256>>>(1, 0, 64, W2, b2);   // hB -> hA
    k_layer_last<<<NNODE / 8, 256>>>(W3, b3);            // hA -> hcat[96]

    k_tail<<<NG, 256>>>(cw1, cb1, cw2, cb2, ow, ob, out);
}

// round 4
// speedup vs baseline: 3.0851x; 1.1473x over previous
#include <cuda_runtime.h>
#include <math.h>

#define NG     128
#define NPER   512
#define NNODE  (NG*NPER)      // 65536
#define NEDGE  1048576
#define KTOP   30
#define DNODE  64
#define DEDGE  32
#define D0     96
#define DL     32
#define TOTALF 97
#define C1N    16
#define C2N    32
#define KW     5
#define PLEN   15
#define CONVL  11
#define DENSE  352
#define OUTD   128

// ---------------- scratch ----------------
__device__ float g_zA  [NNODE*DL];
__device__ float g_zB  [NNODE*DL];
__device__ float g_z3  [NNODE];
__device__ float g_hcat[NNODE*TOTALF];
__device__ float g_degs[NNODE];
__device__ int   g_cnt [NNODE];
__device__ int   g_row [NNODE];
__device__ int   g_cur [NNODE];
__device__ int   g_bsum[64];
__device__ int   g_csrc[NEDGE];
__device__ int   g_ceid[NEDGE];

__device__ __forceinline__ float* zsel(int s) { return s == 0 ? g_zA : g_zB; }

// ---------------- CSR build ----------------
__global__ void k_hist(const int* __restrict__ dst) {
    int base = blockIdx.x * 4096 + threadIdx.x;
    int d0 = dst[base];
    int d1 = dst[base + 1024];
    int d2 = dst[base + 2048];
    int d3 = dst[base + 3072];
    atomicAdd(&g_cnt[d0], 1);
    atomicAdd(&g_cnt[d1], 1);
    atomicAdd(&g_cnt[d2], 1);
    atomicAdd(&g_cnt[d3], 1);
}

__global__ void k_scanA() {
    __shared__ int s[1024];
    int i = blockIdx.x * 1024 + threadIdx.x;
    int v = g_cnt[i];
    s[threadIdx.x] = v; __syncthreads();
    for (int off = 1; off < 1024; off <<= 1) {
        int t = (threadIdx.x >= off) ? s[threadIdx.x - off] : 0;
        __syncthreads();
        s[threadIdx.x] += t;
        __syncthreads();
    }
    g_row[i] = s[threadIdx.x] - v;
    if (threadIdx.x == 1023) g_bsum[blockIdx.x] = s[1023];
}

__global__ void k_scanC() {
    __shared__ int sb[64];
    __shared__ int off;
    if (threadIdx.x < 64)
        sb[threadIdx.x] = (threadIdx.x < blockIdx.x) ? g_bsum[threadIdx.x] : 0;
    __syncthreads();
    if (threadIdx.x < 32) {
        int v = sb[threadIdx.x] + sb[threadIdx.x + 32];
#pragma unroll
        for (int o = 16; o > 0; o >>= 1) v += __shfl_down_sync(0xffffffffu, v, o);
        if (threadIdx.x == 0) off = v;
    }
    __syncthreads();
    int i = blockIdx.x * 1024 + threadIdx.x;
    int rs = g_row[i] + off;
    g_row[i] = rs;
    g_cur[i] = rs;
    g_degs[i] = (float)g_cnt[i] + 1.f;
}

__global__ void k_fill(const int* __restrict__ src, const int* __restrict__ dst) {
    int base = blockIdx.x * 4096 + threadIdx.x;
#pragma unroll
    for (int u = 0; u < 4; u++) {
        int e = base + u * 1024;
        int d = dst[e];
        int p = atomicAdd(&g_cur[d], 1);
        g_csrc[p] = src[e];
        g_ceid[p] = e;
    }
}

// ---------------- build z0 = [nf | e2n] @ W0 ----------------
__global__ void k_build0(const float* __restrict__ nf, const float* __restrict__ ef,
                         const float* __restrict__ W0) {
    __shared__ float Ws[D0 * DL];
    __shared__ float agg[8][D0];
    int tid = threadIdx.x;
    for (int i = tid; i < D0 * DL; i += 256) Ws[i] = W0[i];
    __syncthreads();
    int w = tid >> 5, lane = tid & 31;
    int n = blockIdx.x * 8 + w;
    float f0 = nf[n * DNODE + lane];
    float f1 = nf[n * DNODE + 32 + lane];
    int beg = g_row[n], end = beg + g_cnt[n];
    float acc = 0.f;
    int j = beg;
    for (; j + 7 < end; j += 8) {
        int e0 = g_ceid[j],   e1 = g_ceid[j+1], e2 = g_ceid[j+2], e3 = g_ceid[j+3];
        int e4 = g_ceid[j+4], e5 = g_ceid[j+5], e6 = g_ceid[j+6], e7 = g_ceid[j+7];
        float v0 = ef[e0 * DEDGE + lane];
        float v1 = ef[e1 * DEDGE + lane];
        float v2 = ef[e2 * DEDGE + lane];
        float v3 = ef[e3 * DEDGE + lane];
        float v4 = ef[e4 * DEDGE + lane];
        float v5 = ef[e5 * DEDGE + lane];
        float v6 = ef[e6 * DEDGE + lane];
        float v7 = ef[e7 * DEDGE + lane];
        acc += ((v0 + v1) + (v2 + v3)) + ((v4 + v5) + (v6 + v7));
    }
    for (; j < end; j++) acc += ef[g_ceid[j] * DEDGE + lane];
    agg[w][lane] = f0; agg[w][32 + lane] = f1; agg[w][64 + lane] = acc;
    __syncwarp();
    float z = 0.f;
#pragma unroll
    for (int d = 0; d < D0; d++) z += agg[w][d] * Ws[d * DL + lane];
    g_zA[n * DL + lane] = z;
}

// ---------------- gather z + tanh + project to next z (32->32) ----------------
__global__ void k_gather32(int insel, int outsel, int hcat_off,
                           const float* __restrict__ b, const float* __restrict__ Wn) {
    __shared__ float Ws[DL * DL];
    __shared__ float bs[DL];
    __shared__ float vals[8][DL];
    int tid = threadIdx.x;
    for (int i = tid; i < DL * DL; i += 256) Ws[i] = Wn[i];
    if (tid < DL) bs[tid] = b[tid];
    __syncthreads();
    int w = tid >> 5, lane = tid & 31;
    int n = blockIdx.x * 8 + w;
    const float* z = zsel(insel);
    float a = z[n * DL + lane];
    int beg = g_row[n], end = beg + g_cnt[n];
    int j = beg;
    for (; j + 7 < end; j += 8) {
        int s0 = g_csrc[j],   s1 = g_csrc[j+1], s2 = g_csrc[j+2], s3 = g_csrc[j+3];
        int s4 = g_csrc[j+4], s5 = g_csrc[j+5], s6 = g_csrc[j+6], s7 = g_csrc[j+7];
        float x0 = z[s0 * DL + lane];
        float x1 = z[s1 * DL + lane];
        float x2 = z[s2 * DL + lane];
        float x3 = z[s3 * DL + lane];
        float x4 = z[s4 * DL + lane];
        float x5 = z[s5 * DL + lane];
        float x6 = z[s6 * DL + lane];
        float x7 = z[s7 * DL + lane];
        a += ((x0 + x1) + (x2 + x3)) + ((x4 + x5) + (x6 + x7));
    }
    for (; j < end; j++) a += z[g_csrc[j] * DL + lane];
    float val = tanhf((a + bs[lane]) / g_degs[n]);
    g_hcat[n * TOTALF + hcat_off + lane] = val;
    vals[w][lane] = val;
    __syncwarp();
    float zn = 0.f;
#pragma unroll
    for (int d = 0; d < DL; d++) zn += vals[w][d] * Ws[d * DL + lane];
    zsel(outsel)[n * DL + lane] = zn;
}

// ---------------- gather z + tanh + project to scalar (32->1) ----------------
__global__ void k_gather_p1(int insel, const float* __restrict__ b,
                            const float* __restrict__ W3) {
    int tid = threadIdx.x;
    int w = tid >> 5, lane = tid & 31;
    int n = blockIdx.x * 8 + w;
    const float* z = zsel(insel);
    float a = z[n * DL + lane];
    int beg = g_row[n], end = beg + g_cnt[n];
    int j = beg;
    for (; j + 7 < end; j += 8) {
        int s0 = g_csrc[j],   s1 = g_csrc[j+1], s2 = g_csrc[j+2], s3 = g_csrc[j+3];
        int s4 = g_csrc[j+4], s5 = g_csrc[j+5], s6 = g_csrc[j+6], s7 = g_csrc[j+7];
        float x0 = z[s0 * DL + lane];
        float x1 = z[s1 * DL + lane];
        float x2 = z[s2 * DL + lane];
        float x3 = z[s3 * DL + lane];
        float x4 = z[s4 * DL + lane];
        float x5 = z[s5 * DL + lane];
        float x6 = z[s6 * DL + lane];
        float x7 = z[s7 * DL + lane];
        a += ((x0 + x1) + (x2 + x3)) + ((x4 + x5) + (x6 + x7));
    }
    for (; j < end; j++) a += z[g_csrc[j] * DL + lane];
    float val = tanhf((a + b[lane]) / g_degs[n]);
    g_hcat[n * TOTALF + 64 + lane] = val;
    float v = val * W3[lane];
#pragma unroll
    for (int off = 16; off > 0; off >>= 1) v += __shfl_xor_sync(0xffffffffu, v, off);
    if (lane == 0) g_z3[n] = v;
}

// ---------------- final layer: scalar gather ----------------
__global__ void k_gather3(const float* __restrict__ b3) {
    int n = blockIdx.x * 256 + threadIdx.x;
    float bb = b3[0];
    float a = g_z3[n];
    int beg = g_row[n], end = beg + g_cnt[n];
    int j = beg;
    float a1 = 0.f, a2 = 0.f, a3 = 0.f;
    for (; j + 3 < end; j += 4) {
        int s0 = g_csrc[j], s1 = g_csrc[j+1], s2 = g_csrc[j+2], s3 = g_csrc[j+3];
        a  += g_z3[s0];
        a1 += g_z3[s1];
        a2 += g_z3[s2];
        a3 += g_z3[s3];
    }
    for (; j < end; j++) a += g_z3[g_csrc[j]];
    a = (a + a1) + (a2 + a3);
    g_hcat[n * TOTALF + 96] = tanhf((a + bb) / g_degs[n]);
}

// ---------------- fused per-group topk + head ----------------
__global__ void k_tail(const float* __restrict__ cw1, const float* __restrict__ cb1,
                       const float* __restrict__ cw2, const float* __restrict__ cb2,
                       const float* __restrict__ ow,  const float* __restrict__ ob,
                       float* __restrict__ out) {
    __shared__ float v[NPER];
    __shared__ int   ix[NPER];
    __shared__ float pooled[KTOP][TOTALF];
    __shared__ float c1s[C1N][KTOP];
    __shared__ float c1p[C1N][PLEN];
    __shared__ float c2s[DENSE];
    int g = blockIdx.x, tid = threadIdx.x;      // 256 threads

    for (int i = tid; i < NPER; i += 256) {
        v[i] = g_hcat[(g * NPER + i) * TOTALF + 96];
        ix[i] = i;
    }
    __syncthreads();
    for (int k = 2; k <= NPER; k <<= 1) {
        for (int j = k >> 1; j > 0; j >>= 1) {
            for (int i = tid; i < NPER; i += 256) {
                int p = i ^ j;
                if (p > i) {
                    float va = v[i], vb = v[p];
                    int ia = ix[i], ib = ix[p];
                    bool a_first = (va > vb) || (va == vb && ia < ib);
                    bool up = ((i & k) == 0);
                    if (up ? !a_first : a_first) {
                        v[i] = vb; v[p] = va;
                        ix[i] = ib; ix[p] = ia;
                    }
                }
            }
            __syncthreads();
        }
    }

    for (int t = tid; t < KTOP * TOTALF; t += 256) {
        int kk = t / TOTALF, d = t - kk * TOTALF;
        int node = g * NPER + ix[kk];
        pooled[kk][d] = g_hcat[node * TOTALF + d];
    }
    __syncthreads();

    for (int t = tid; t < C1N * KTOP; t += 256) {
        int o = t / KTOP, kk = t - o * KTOP;
        float s = cb1[o];
#pragma unroll 8
        for (int d = 0; d < TOTALF; d++) s += pooled[kk][d] * cw1[o * TOTALF + d];
        c1s[o][kk] = fmaxf(s, 0.f);
    }
    __syncthreads();

    for (int t = tid; t < C1N * PLEN; t += 256) {
        int o = t / PLEN, j = t - o * PLEN;
        c1p[o][j] = fmaxf(c1s[o][2 * j], c1s[o][2 * j + 1]);
    }
    __syncthreads();

    for (int t = tid; t < C2N * CONVL; t += 256) {
        int o = t / CONVL, j = t - o * CONVL;
        float s = cb2[o];
#pragma unroll
        for (int i = 0; i < C1N; i++)
#pragma unroll
            for (int u = 0; u < KW; u++)
                s += c1p[i][j + u] * cw2[(o * C1N + i) * KW + u];
        c2s[o * CONVL + j] = fmaxf(s, 0.f);
    }
    __syncthreads();

    if (tid < OUTD) {
        int u = tid;
        float s = ob[u];
#pragma unroll 8
        for (int f = 0; f < DENSE; f++) s += c2s[f] * ow[f * OUTD + u];
        out[g * OUTD + u] = fmaxf(s, 0.f);
    }
}

// ---------------- launch ----------------
extern "C" void kernel_launch(void* const* d_in, const int* in_sizes, int n_in,
                              void* d_out, int out_size) {
    const float* node_feat = (const float*)d_in[0];
    const float* edge_feat = (const float*)d_in[1];
    const int*   edge_src  = (const int*)  d_in[2];
    const int*   edge_dst  = (const int*)  d_in[3];
    const float* W0 = (const float*)d_in[4];
    const float* b0 = (const float*)d_in[5];
    const float* W1 = (const float*)d_in[6];
    const float* b1 = (const float*)d_in[7];
    const float* W2 = (const float*)d_in[8];
    const float* b2 = (const float*)d_in[9];
    const float* W3 = (const float*)d_in[10];
    const float* b3 = (const float*)d_in[11];
    const float* cw1 = (const float*)d_in[12];
    const float* cb1 = (const float*)d_in[13];
    const float* cw2 = (const float*)d_in[14];
    const float* cb2 = (const float*)d_in[15];
    const float* ow  = (const float*)d_in[16];
    const float* ob  = (const float*)d_in[17];
    float* out = (float*)d_out;

    void* cnt_ptr = nullptr;
    cudaGetSymbolAddress(&cnt_ptr, g_cnt);
    cudaMemsetAsync(cnt_ptr, 0, NNODE * sizeof(int), 0);

    k_hist <<<256, 1024>>>(edge_dst);
    k_scanA<<<64, 1024>>>();
    k_scanC<<<64, 1024>>>();
    k_fill <<<256, 1024>>>(edge_src, edge_dst);

    k_build0  <<<NNODE / 8, 256>>>(node_feat, edge_feat, W0);   // -> zA
    k_gather32<<<NNODE / 8, 256>>>(0, 1, 0,  b0, W1);           // zA -> hcat0, zB
    k_gather32<<<NNODE / 8, 256>>>(1, 0, 32, b1, W2);           // zB -> hcat32, zA
    k_gather_p1<<<NNODE / 8, 256>>>(0, b2, W3);                 // zA -> hcat64, z3
    k_gather3 <<<NNODE / 256, 256>>>(b3);                       // z3 -> hcat96

    k_tail<<<NG, 256>>>(cw1, cb1, cw2, cb2, ow, ob, out);
}

// round 6
// speedup vs baseline: 3.1165x; 1.0102x over previous
#include <cuda_runtime.h>
#include <math.h>

#define NG     128
#define NPER   512
#define NNODE  (NG*NPER)      // 65536
#define NEDGE  1048576
#define KTOP   30
#define DNODE  64
#define DEDGE  32
#define D0     96
#define DL     32
#define TOTALF 97
#define C1N    16
#define C2N    32
#define KW     5
#define PLEN   15
#define CONVL  11
#define DENSE  352
#define OUTD   128

// ---------------- scratch ----------------
__device__ float  g_zA [NNODE*DL];
__device__ float  g_zB [NNODE*DL];
__device__ float  g_z3 [NNODE];
__device__ float  g_hcat[NNODE*TOTALF];
__device__ float  g_degs[NNODE];
__device__ int    g_cnt [NNODE];
__device__ int    g_row [NNODE];
__device__ int    g_cur [NNODE];
__device__ int    g_bsum[64];
__device__ int2   g_pair[NEDGE];    // .x = src node, .y = edge id (dst-sorted)

__device__ __forceinline__ float* zsel(int s) { return s == 0 ? g_zA : g_zB; }

// ---------------- CSR build ----------------
__global__ void k_hist(const int* __restrict__ dst) {
    int i = blockIdx.x * 1024 + threadIdx.x;
    int4 d = ((const int4*)dst)[i];
    atomicAdd(&g_cnt[d.x], 1);
    atomicAdd(&g_cnt[d.y], 1);
    atomicAdd(&g_cnt[d.z], 1);
    atomicAdd(&g_cnt[d.w], 1);
}

__global__ void k_scanA() {
    __shared__ int s[1024];
    int i = blockIdx.x * 1024 + threadIdx.x;
    int v = g_cnt[i];
    s[threadIdx.x] = v; __syncthreads();
    for (int off = 1; off < 1024; off <<= 1) {
        int t = (threadIdx.x >= off) ? s[threadIdx.x - off] : 0;
        __syncthreads();
        s[threadIdx.x] += t;
        __syncthreads();
    }
    g_row[i] = s[threadIdx.x] - v;
    if (threadIdx.x == 1023) g_bsum[blockIdx.x] = s[1023];
}

__global__ void k_scanC() {
    __shared__ int sb[64];
    __shared__ int off;
    if (threadIdx.x < 64)
        sb[threadIdx.x] = (threadIdx.x < blockIdx.x) ? g_bsum[threadIdx.x] : 0;
    __syncthreads();
    if (threadIdx.x < 32) {
        int v = sb[threadIdx.x] + sb[threadIdx.x + 32];
#pragma unroll
        for (int o = 16; o > 0; o >>= 1) v += __shfl_down_sync(0xffffffffu, v, o);
        if (threadIdx.x == 0) off = v;
    }
    __syncthreads();
    int i = blockIdx.x * 1024 + threadIdx.x;
    int rs = g_row[i] + off;
    g_row[i] = rs;
    g_cur[i] = rs;
    g_degs[i] = (float)g_cnt[i] + 1.f;
}

__global__ void k_fill(const int* __restrict__ src, const int* __restrict__ dst) {
    int i = blockIdx.x * 1024 + threadIdx.x;
    int4 d = ((const int4*)dst)[i];
    int4 s = ((const int4*)src)[i];
    int e = i * 4;
    int p0 = atomicAdd(&g_cur[d.x], 1);
    g_pair[p0] = make_int2(s.x, e);
    int p1 = atomicAdd(&g_cur[d.y], 1);
    g_pair[p1] = make_int2(s.y, e + 1);
    int p2 = atomicAdd(&g_cur[d.z], 1);
    g_pair[p2] = make_int2(s.z, e + 2);
    int p3 = atomicAdd(&g_cur[d.w], 1);
    g_pair[p3] = make_int2(s.w, e + 3);
}

// ---------------- build z0 = [nf | e2n] @ W0 ----------------
__global__ void k_build0(const float* __restrict__ nf, const float* __restrict__ ef,
                         const float* __restrict__ W0) {
    __shared__ float Ws[D0 * DL];
    __shared__ float agg[8][D0];
    int tid = threadIdx.x;
    for (int i = tid; i < D0 * DL; i += 256) Ws[i] = W0[i];
    __syncthreads();
    int w = tid >> 5, lane = tid & 31;
    int n = blockIdx.x * 8 + w;
    float f0 = nf[n * DNODE + lane];
    float f1 = nf[n * DNODE + 32 + lane];
    int beg = g_row[n], end = beg + g_cnt[n];
    float acc = 0.f;
    int j = beg;
    for (; j + 7 < end; j += 8) {
        int e0 = g_pair[j].y,   e1 = g_pair[j+1].y, e2 = g_pair[j+2].y, e3 = g_pair[j+3].y;
        int e4 = g_pair[j+4].y, e5 = g_pair[j+5].y, e6 = g_pair[j+6].y, e7 = g_pair[j+7].y;
        float v0 = ef[e0 * DEDGE + lane];
        float v1 = ef[e1 * DEDGE + lane];
        float v2 = ef[e2 * DEDGE + lane];
        float v3 = ef[e3 * DEDGE + lane];
        float v4 = ef[e4 * DEDGE + lane];
        float v5 = ef[e5 * DEDGE + lane];
        float v6 = ef[e6 * DEDGE + lane];
        float v7 = ef[e7 * DEDGE + lane];
        acc += ((v0 + v1) + (v2 + v3)) + ((v4 + v5) + (v6 + v7));
    }
    for (; j < end; j++) acc += ef[g_pair[j].y * DEDGE + lane];
    agg[w][lane] = f0; agg[w][32 + lane] = f1; agg[w][64 + lane] = acc;
    __syncwarp();
    float z = 0.f;
#pragma unroll
    for (int d = 0; d < D0; d++) z += agg[w][d] * Ws[d * DL + lane];
    g_zA[n * DL + lane] = z;
}

// ---------------- gather z + tanh + project to next z (32->32) ----------------
__global__ void k_gather32(int insel, int outsel, int hcat_off,
                           const float* __restrict__ b, const float* __restrict__ Wn) {
    __shared__ float Ws[DL * DL];
    __shared__ float bs[DL];
    __shared__ float vals[8][DL];
    int tid = threadIdx.x;
    for (int i = tid; i < DL * DL; i += 256) Ws[i] = Wn[i];
    if (tid < DL) bs[tid] = b[tid];
    __syncthreads();
    int w = tid >> 5, lane = tid & 31;
    int n = blockIdx.x * 8 + w;
    const float* z = zsel(insel);
    float a = z[n * DL + lane];
    int beg = g_row[n], end = beg + g_cnt[n];
    int j = beg;
    for (; j + 7 < end; j += 8) {
        int s0 = g_pair[j].x,   s1 = g_pair[j+1].x, s2 = g_pair[j+2].x, s3 = g_pair[j+3].x;
        int s4 = g_pair[j+4].x, s5 = g_pair[j+5].x, s6 = g_pair[j+6].x, s7 = g_pair[j+7].x;
        float x0 = z[s0 * DL + lane];
        float x1 = z[s1 * DL + lane];
        float x2 = z[s2 * DL + lane];
        float x3 = z[s3 * DL + lane];
        float x4 = z[s4 * DL + lane];
        float x5 = z[s5 * DL + lane];
        float x6 = z[s6 * DL + lane];
        float x7 = z[s7 * DL + lane];
        a += ((x0 + x1) + (x2 + x3)) + ((x4 + x5) + (x6 + x7));
    }
    for (; j < end; j++) a += z[g_pair[j].x * DL + lane];
    float val = tanhf((a + bs[lane]) / g_degs[n]);
    g_hcat[n * TOTALF + hcat_off + lane] = val;
    vals[w][lane] = val;
    __syncwarp();
    float zn = 0.f;
#pragma unroll
    for (int d = 0; d < DL; d++) zn += vals[w][d] * Ws[d * DL + lane];
    zsel(outsel)[n * DL + lane] = zn;
}

// ---------------- gather z + tanh + project to scalar (32->1) ----------------
__global__ void k_gather_p1(int insel, const float* __restrict__ b,
                            const float* __restrict__ W3) {
    int tid = threadIdx.x;
    int w = tid >> 5, lane = tid & 31;
    int n = blockIdx.x * 8 + w;
    const float* z = zsel(insel);
    float a = z[n * DL + lane];
    int beg = g_row[n], end = beg + g_cnt[n];
    int j = beg;
    for (; j + 7 < end; j += 8) {
        int s0 = g_pair[j].x,   s1 = g_pair[j+1].x, s2 = g_pair[j+2].x, s3 = g_pair[j+3].x;
        int s4 = g_pair[j+4].x, s5 = g_pair[j+5].x, s6 = g_pair[j+6].x, s7 = g_pair[j+7].x;
        float x0 = z[s0 * DL + lane];
        float x1 = z[s1 * DL + lane];
        float x2 = z[s2 * DL + lane];
        float x3 = z[s3 * DL + lane];
        float x4 = z[s4 * DL + lane];
        float x5 = z[s5 * DL + lane];
        float x6 = z[s6 * DL + lane];
        float x7 = z[s7 * DL + lane];
        a += ((x0 + x1) + (x2 + x3)) + ((x4 + x5) + (x6 + x7));
    }
    for (; j < end; j++) a += z[g_pair[j].x * DL + lane];
    float val = tanhf((a + b[lane]) / g_degs[n]);
    g_hcat[n * TOTALF + 64 + lane] = val;
    float v = val * W3[lane];
#pragma unroll
    for (int off = 16; off > 0; off >>= 1) v += __shfl_xor_sync(0xffffffffu, v, off);
    if (lane == 0) g_z3[n] = v;
}

// ---------------- final layer: scalar gather ----------------
__global__ void k_gather3(const float* __restrict__ b3) {
    int n = blockIdx.x * 256 + threadIdx.x;
    float bb = b3[0];
    float a = g_z3[n];
    int beg = g_row[n], end = beg + g_cnt[n];
    int j = beg;
    float a1 = 0.f, a2 = 0.f, a3 = 0.f;
    for (; j + 3 < end; j += 4) {
        a  += g_z3[g_pair[j].x];
        a1 += g_z3[g_pair[j+1].x];
        a2 += g_z3[g_pair[j+2].x];
        a3 += g_z3[g_pair[j+3].x];
    }
    for (; j < end; j++) a += g_z3[g_pair[j].x];
    a = (a + a1) + (a2 + a3);
    g_hcat[n * TOTALF + 96] = tanhf((a + bb) / g_degs[n]);
}

// ---------------- fused per-group topk + head ----------------
__global__ void k_tail(const float* __restrict__ cw1, const float* __restrict__ cb1,
                       const float* __restrict__ cw2, const float* __restrict__ cb2,
                       const float* __restrict__ ow,  const float* __restrict__ ob,
                       float* __restrict__ out) {
    __shared__ float v[NPER];
    __shared__ int   ix[NPER];
    __shared__ float pooled[KTOP][TOTALF];
    __shared__ float c1s[C1N][KTOP];
    __shared__ float c1p[C1N][PLEN];
    __shared__ float c2s[DENSE];
    int g = blockIdx.x, tid = threadIdx.x;      // 256 threads

    for (int i = tid; i < NPER; i += 256) {
        v[i] = g_hcat[(g * NPER + i) * TOTALF + 96];
        ix[i] = i;
    }
    __syncthreads();
    for (int k = 2; k <= NPER; k <<= 1) {
        for (int j = k >> 1; j > 0; j >>= 1) {
            for (int i = tid; i < NPER; i += 256) {
                int p = i ^ j;
                if (p > i) {
                    float va = v[i], vb = v[p];
                    int ia = ix[i], ib = ix[p];
                    bool a_first = (va > vb) || (va == vb && ia < ib);
                    bool up = ((i & k) == 0);
                    if (up ? !a_first : a_first) {
                        v[i] = vb; v[p] = va;
                        ix[i] = ib; ix[p] = ia;
                    }
                }
            }
            __syncthreads();
        }
    }

    for (int t = tid; t < KTOP * TOTALF; t += 256) {
        int kk = t / TOTALF, d = t - kk * TOTALF;
        int node = g * NPER + ix[kk];
        pooled[kk][d] = g_hcat[node * TOTALF + d];
    }
    __syncthreads();

    for (int t = tid; t < C1N * KTOP; t += 256) {
        int o = t / KTOP, kk = t - o * KTOP;
        float s = cb1[o];
#pragma unroll 8
        for (int d = 0; d < TOTALF; d++) s += pooled[kk][d] * cw1[o * TOTALF + d];
        c1s[o][kk] = fmaxf(s, 0.f);
    }
    __syncthreads();

    for (int t = tid; t < C1N * PLEN; t += 256) {
        int o = t / PLEN, j = t - o * PLEN;
        c1p[o][j] = fmaxf(c1s[o][2 * j], c1s[o][2 * j + 1]);
    }
    __syncthreads();

    for (int t = tid; t < C2N * CONVL; t += 256) {
        int o = t / CONVL, j = t - o * CONVL;
        float s = cb2[o];
#pragma unroll
        for (int i = 0; i < C1N; i++)
#pragma unroll
            for (int u = 0; u < KW; u++)
                s += c1p[i][j + u] * cw2[(o * C1N + i) * KW + u];
        c2s[o * CONVL + j] = fmaxf(s, 0.f);
    }
    __syncthreads();

    if (tid < OUTD) {
        int u = tid;
        float s = ob[u];
#pragma unroll 8
        for (int f = 0; f < DENSE; f++) s += c2s[f] * ow[f * OUTD + u];
        out[g * OUTD + u] = fmaxf(s, 0.f);
    }
}

// ---------------- launch ----------------
extern "C" void kernel_launch(void* const* d_in, const int* in_sizes, int n_in,
                              void* d_out, int out_size) {
    const float* node_feat = (const float*)d_in[0];
    const float* edge_feat = (const float*)d_in[1];
    const int*   edge_src  = (const int*)  d_in[2];
    const int*   edge_dst  = (const int*)  d_in[3];
    const float* W0 = (const float*)d_in[4];
    const float* b0 = (const float*)d_in[5];
    const float* W1 = (const float*)d_in[6];
    const float* b1 = (const float*)d_in[7];
    const float* W2 = (const float*)d_in[8];
    const float* b2 = (const float*)d_in[9];
    const float* W3 = (const float*)d_in[10];
    const float* b3 = (const float*)d_in[11];
    const float* cw1 = (const float*)d_in[12];
    const float* cb1 = (const float*)d_in[13];
    const float* cw2 = (const float*)d_in[14];
    const float* cb2 = (const float*)d_in[15];
    const float* ow  = (const float*)d_in[16];
    const float* ob  = (const float*)d_in[17];
    float* out = (float*)d_out;

    void* cnt_ptr = nullptr;
    cudaGetSymbolAddress(&cnt_ptr, g_cnt);
    cudaMemsetAsync(cnt_ptr, 0, NNODE * sizeof(int), 0);

    k_hist <<<NEDGE / 4096, 1024>>>(edge_dst);
    k_scanA<<<64, 1024>>>();
    k_scanC<<<64, 1024>>>();
    k_fill <<<NEDGE / 4096, 1024>>>(edge_src, edge_dst);

    k_build0   <<<NNODE / 8, 256>>>(node_feat, edge_feat, W0);  // -> zA
    k_gather32 <<<NNODE / 8, 256>>>(0, 1, 0,  b0, W1);          // zA -> hcat0, zB
    k_gather32 <<<NNODE / 8, 256>>>(1, 0, 32, b1, W2);          // zB -> hcat32, zA
    k_gather_p1<<<NNODE / 8, 256>>>(0, b2, W3);                 // zA -> hcat64, z3
    k_gather3  <<<NNODE / 256, 256>>>(b3);                      // z3 -> hcat96

    k_tail<<<NG, 256>>>(cw1, cb1, cw2, cb2, ow, ob, out);
}